// round 17
// baseline (speedup 1.0000x reference)
#include <cuda_runtime.h>
#include <cuda_fp16.h>
#include <cstdint>

#define TOTAL   9216
#define DIM     2048
#define HEADS   16
#define HD      128
#define FDIM    8192
#define QKV3    6144

// ---------------- scratch (device globals: allocation-free) ----------------
__device__ __half g_ln  [(size_t)TOTAL * DIM];
__device__ __half g_qkv [(size_t)TOTAL * QKV3];
__device__ __half g_attn[(size_t)TOTAL * DIM];
__device__ float  g_h2  [(size_t)TOTAL * DIM];
__device__ __half g_gu  [(size_t)TOTAL * FDIM];     // fused up*sigmoid(gate)
// fp16 weight copies
__device__ __half g_wqkv [(size_t)QKV3 * DIM];
__device__ __half g_wout [(size_t)DIM * DIM];
__device__ __half g_wgu  [(size_t)2 * FDIM * DIM];  // interleaved gate/up rows
__device__ __half g_wdown[(size_t)DIM * FDIM];

__device__ const int c_seqlen[8] = {512, 1024, 2048, 768, 1536, 896, 1280, 1152};

// ---------------- helpers ----------------
__device__ __forceinline__ void mma_f16(float* c, const uint32_t* a, const uint32_t* b) {
    asm("mma.sync.aligned.m16n8k16.row.col.f32.f16.f16.f32 "
        "{%0,%1,%2,%3},{%4,%5,%6,%7},{%8,%9},{%0,%1,%2,%3};"
        : "+f"(c[0]), "+f"(c[1]), "+f"(c[2]), "+f"(c[3])
        : "r"(a[0]), "r"(a[1]), "r"(a[2]), "r"(a[3]), "r"(b[0]), "r"(b[1]));
}

__device__ __forceinline__ void ldsm_x4(uint32_t* r, uint32_t addr) {
    asm volatile("ldmatrix.sync.aligned.m8n8.x4.shared.b16 {%0,%1,%2,%3}, [%4];"
        : "=r"(r[0]), "=r"(r[1]), "=r"(r[2]), "=r"(r[3]) : "r"(addr));
}
__device__ __forceinline__ void ldsm_x4_t(uint32_t* r, uint32_t addr) {
    asm volatile("ldmatrix.sync.aligned.m8n8.x4.trans.shared.b16 {%0,%1,%2,%3}, [%4];"
        : "=r"(r[0]), "=r"(r[1]), "=r"(r[2]), "=r"(r[3]) : "r"(addr));
}

__device__ __forceinline__ void cp_async16(void* smem_dst, const void* gmem_src) {
    uint32_t s = (uint32_t)__cvta_generic_to_shared(smem_dst);
    asm volatile("cp.async.cg.shared.global [%0], [%1], 16;" :: "r"(s), "l"(gmem_src));
}

// mbarrier primitives
__device__ __forceinline__ void mbar_init(uint32_t addr, uint32_t count) {
    asm volatile("mbarrier.init.shared.b64 [%0], %1;" :: "r"(addr), "r"(count) : "memory");
}
__device__ __forceinline__ void mbar_arrive(uint32_t addr) {
    asm volatile("mbarrier.arrive.shared.b64 _, [%0];" :: "r"(addr) : "memory");
}
__device__ __forceinline__ void cp_mbar_arrive(uint32_t addr) {
    asm volatile("cp.async.mbarrier.arrive.noinc.shared.b64 [%0];" :: "r"(addr) : "memory");
}
__device__ __forceinline__ void mbar_wait(uint32_t addr, uint32_t parity) {
    asm volatile(
        "{\n\t.reg .pred P;\n\t"
        "W%=:\n\t"
        "mbarrier.try_wait.parity.shared.b64 P, [%0], %1;\n\t"
        "@!P bra W%=;\n\t}"
        :: "r"(addr), "r"(parity) : "memory");
}

// ================= fp16 GEMM, barrier-free mbarrier pipeline =================
// 128x128 tile, 256 threads, K-chunk 64, 3-stage cp.async + per-stage mbarriers.
#define HSTRIDE 72
#define A_HALFS (128 * HSTRIDE)
#define STAGE_HALFS (2 * A_HALFS)
#define STAGE_BYTES (STAGE_HALFS * 2)
#define GEMM_SMEM_BYTES (3 * STAGE_BYTES + 64)

__device__ __forceinline__ void h_load_stage(const __half* __restrict__ Ab,
                                             const __half* __restrict__ Bb,
                                             int K, __half* As, __half* Bs, int tid)
{
    #pragma unroll
    for (int j = 0; j < 4; j++) {
        int id = tid + j * 256;
        int r = id >> 3, g = (id & 7) << 3;
        cp_async16(As + r * HSTRIDE + g, Ab + (size_t)r * K + g);
        cp_async16(Bs + r * HSTRIDE + g, Bb + (size_t)r * K + g);
    }
}

// Output modes: Cg (gated fp16, N/2 cols) > Ch (fp16) > Cf (fp32)
__global__ __launch_bounds__(256, 2) void gemm_f16_kernel(
    const __half* __restrict__ A, const __half* __restrict__ B,
    const float* __restrict__ bias, const float* __restrict__ resid,
    float* __restrict__ Cf, __half* __restrict__ Ch, __half* __restrict__ Cg,
    int M, int N, int K)
{
    extern __shared__ __half hsm[];
    const uint32_t smemBase = (uint32_t)__cvta_generic_to_shared(hsm);

    const int tid  = threadIdx.x;
    const int lane = tid & 31, warp = tid >> 5;
    const int lq = lane >> 2, lr = lane & 3;
    const int wm = (warp >> 2) * 64, wn = (warp & 3) * 32;
    const int bm = blockIdx.y * 128, bn = blockIdx.x * 128;

    const int tr = lane & 7, th = (lane >> 3) & 1, tq = lane >> 4;
    const uint32_t aoff = (uint32_t)(((wm + tr + th * 8) * HSTRIDE + tq * 8) * 2);
    const uint32_t boff = (uint32_t)(((wn + tr + th * 8) * HSTRIDE + tq * 8) * 2);

    const uint32_t barB = smemBase + 3 * STAGE_BYTES;

    float acc[4][4][4];
    #pragma unroll
    for (int mf = 0; mf < 4; mf++)
        #pragma unroll
        for (int nf = 0; nf < 4; nf++)
            #pragma unroll
            for (int e = 0; e < 4; e++) acc[mf][nf][e] = 0.f;

    const __half* Abase = A + (size_t)bm * K;
    const __half* Bbase = B + (size_t)bn * K;
    const int nk = K >> 6;

    if (tid < 3) {
        mbar_init(barB + 8 * tid, 256);        // full[s]
        mbar_init(barB + 24 + 8 * tid, 256);   // empty[s]
    }
    __syncthreads();

    #pragma unroll
    for (int s = 0; s < 2; s++) {
        __half* As = hsm + s * STAGE_HALFS;
        __half* Bs = As + A_HALFS;
        h_load_stage(Abase + s * 64, Bbase + s * 64, K, As, Bs, tid);
        cp_mbar_arrive(barB + 8 * s);
    }

    for (int i = 0; i < nk; i++) {
        const int st = i % 3;
        mbar_wait(barB + 8 * st, (uint32_t)((i / 3) & 1));

        const uint32_t stOff = smemBase + (uint32_t)(st * STAGE_BYTES);
        const uint32_t aBase = stOff + aoff;
        const uint32_t bBase = stOff + (uint32_t)(A_HALFS * 2) + boff;

        #pragma unroll
        for (int ks = 0; ks < 4; ks++) {
            const uint32_t kOff = (uint32_t)(ks * 32);
            uint32_t af[4][4];
            #pragma unroll
            for (int mf = 0; mf < 4; mf++)
                ldsm_x4(af[mf], aBase + (uint32_t)(mf * 16 * HSTRIDE * 2) + kOff);
            uint32_t b0[4], b1[4];
            ldsm_x4(b0, bBase + kOff);
            ldsm_x4(b1, bBase + (uint32_t)(16 * HSTRIDE * 2) + kOff);
            uint32_t bf[4][2] = {{b0[0], b0[2]}, {b0[1], b0[3]},
                                 {b1[0], b1[2]}, {b1[1], b1[3]}};
            #pragma unroll
            for (int mf = 0; mf < 4; mf++)
                #pragma unroll
                for (int nf = 0; nf < 4; nf++)
                    mma_f16(acc[mf][nf], af[mf], bf[nf]);
        }
        mbar_arrive(barB + 24 + 8 * st);

        const int c = i + 2;
        if (c < nk) {
            const int ps = c % 3;
            if (c >= 3)
                mbar_wait(barB + 24 + 8 * ps, (uint32_t)(((c / 3) - 1) & 1));
            __half* Ad = hsm + ps * STAGE_HALFS;
            __half* Bd = Ad + A_HALFS;
            h_load_stage(Abase + (size_t)c * 64, Bbase + (size_t)c * 64, K, Ad, Bd, tid);
            cp_mbar_arrive(barB + 8 * ps);
        }
    }

    // epilogue
    #pragma unroll
    for (int mf = 0; mf < 4; mf++) {
        #pragma unroll
        for (int nf = 0; nf < 4; nf++) {
            int r0 = bm + wm + mf * 16 + lq;
            int c0 = bn + wn + nf * 8 + lr * 2;
            float b0 = 0.f, b1 = 0.f;
            if (bias) { b0 = bias[c0]; b1 = bias[c0 + 1]; }
            float2 v0 = make_float2(acc[mf][nf][0] + b0, acc[mf][nf][1] + b1);
            float2 v1 = make_float2(acc[mf][nf][2] + b0, acc[mf][nf][3] + b1);
            if (resid) {
                float2 ra = *reinterpret_cast<const float2*>(resid + (size_t)r0 * N + c0);
                float2 rb = *reinterpret_cast<const float2*>(resid + (size_t)(r0 + 8) * N + c0);
                v0.x += ra.x; v0.y += ra.y;
                v1.x += rb.x; v1.y += rb.y;
            }
            if (Cg) {
                int f = c0 >> 1;
                float h0 = v0.y / (1.f + __expf(-v0.x));
                float h1 = v1.y / (1.f + __expf(-v1.x));
                Cg[(size_t)r0 * (N >> 1) + f]       = __float2half_rn(h0);
                Cg[(size_t)(r0 + 8) * (N >> 1) + f] = __float2half_rn(h1);
            } else if (Ch) {
                *reinterpret_cast<__half2*>(Ch + (size_t)r0 * N + c0) =
                    __floats2half2_rn(v0.x, v0.y);
                *reinterpret_cast<__half2*>(Ch + (size_t)(r0 + 8) * N + c0) =
                    __floats2half2_rn(v1.x, v1.y);
            } else {
                *reinterpret_cast<float2*>(Cf + (size_t)r0 * N + c0) = v0;
                *reinterpret_cast<float2*>(Cf + (size_t)(r0 + 8) * N + c0) = v1;
            }
        }
    }
}

// ---------------- weight converts ----------------
__global__ __launch_bounds__(256) void cvtw_kernel(const float4* __restrict__ in,
                                                   __half2* __restrict__ out, int n4)
{
    int i = blockIdx.x * blockDim.x + threadIdx.x;
    if (i < n4) {
        float4 v = in[i];
        out[2 * i]     = __floats2half2_rn(v.x, v.y);
        out[2 * i + 1] = __floats2half2_rn(v.z, v.w);
    }
}

// interleave gate/up rows: out row 2f = gate f, row 2f+1 = up f
__global__ __launch_bounds__(256) void cvtw2_kernel(const float4* __restrict__ gw,
                                                    const float4* __restrict__ uw,
                                                    __half2* __restrict__ out, int n4)
{
    int i = blockIdx.x * blockDim.x + threadIdx.x;
    if (i < n4) {
        int f = i >> 9;            // DIM/4 = 512 float4 per row
        int c4 = i & 511;
        float4 g = gw[i];
        float4 u = uw[i];
        size_t og = ((size_t)(2 * f) * 512 + c4) * 2;
        size_t ou = ((size_t)(2 * f + 1) * 512 + c4) * 2;
        out[og]     = __floats2half2_rn(g.x, g.y);
        out[og + 1] = __floats2half2_rn(g.z, g.w);
        out[ou]     = __floats2half2_rn(u.x, u.y);
        out[ou + 1] = __floats2half2_rn(u.z, u.w);
    }
}

// ---------------- RMSNorm (fp32 in, fp16 out) ----------------
__global__ __launch_bounds__(256) void rmsnorm_kernel(const float* __restrict__ x,
                                                      const float* __restrict__ w,
                                                      __half* __restrict__ y)
{
    int row = blockIdx.x;
    const float4* xr = reinterpret_cast<const float4*>(x + (size_t)row * DIM);
    __half2*      yr = reinterpret_cast<__half2*>(y + (size_t)row * DIM);
    const float4* wr = reinterpret_cast<const float4*>(w);
    int tid = threadIdx.x;

    float4 v0 = xr[tid];
    float4 v1 = xr[tid + 256];
    float ss = v0.x*v0.x + v0.y*v0.y + v0.z*v0.z + v0.w*v0.w
             + v1.x*v1.x + v1.y*v1.y + v1.z*v1.z + v1.w*v1.w;
    #pragma unroll
    for (int o = 16; o; o >>= 1) ss += __shfl_xor_sync(0xffffffffu, ss, o);

    __shared__ float red[8];
    __shared__ float stot;
    if ((tid & 31) == 0) red[tid >> 5] = ss;
    __syncthreads();
    if (tid == 0) {
        float t = 0.f;
        #pragma unroll
        for (int i = 0; i < 8; i++) t += red[i];
        stot = rsqrtf(t * (1.0f / (float)DIM) + 1e-6f);
    }
    __syncthreads();
    float r = stot;

    float4 w0 = wr[tid], w1 = wr[tid + 256];
    yr[2 * tid]             = __floats2half2_rn(v0.x*r*w0.x, v0.y*r*w0.y);
    yr[2 * tid + 1]         = __floats2half2_rn(v0.z*r*w0.z, v0.w*r*w0.w);
    yr[2 * (tid + 256)]     = __floats2half2_rn(v1.x*r*w1.x, v1.y*r*w1.y);
    yr[2 * (tid + 256) + 1] = __floats2half2_rn(v1.z*r*w1.z, v1.w*r*w1.w);
}

// ---------------- Flash attention v5: within-warp S/PV software pipeline ----------------
// Per iter t: S(t) mma -> PV(t-1) mma -> softmax(t). PV(t-1) fills the tensor
// pipe while the warp runs softmax ALU/MUFU. K prefetch dist 2, V dist 1, split
// K/V mbarrier protocols. P(t) persists in regs; drain PV after loop. 2 CTAs/SM.
#define AQ_STRIDE 136
#define AK_STRIDE 136
#define AV_STRIDE 136
#define LOG2E 1.4426950408889634f

#define AQ_HALFS (128 * AQ_STRIDE)
#define AK_HALFS (64 * AK_STRIDE)
#define AV_HALFS (64 * AV_STRIDE)
#define ATTN_DATA_BYTES ((AQ_HALFS + 2 * AK_HALFS + 2 * AV_HALFS) * 2)
#define ATTN_SMEM_BYTES (ATTN_DATA_BYTES + 128)

__global__ __launch_bounds__(256, 2) void attn_kernel(const __half* __restrict__ qkv,
                                                      __half* __restrict__ out)
{
    extern __shared__ __half asmem[];
    __half* Qs = asmem;
    __half* Ks = Qs + AQ_HALFS;
    __half* Vs = Ks + 2 * AK_HALFS;
    const uint32_t smemBase = (uint32_t)__cvta_generic_to_shared(asmem);
    const uint32_t QsB = smemBase;
    const uint32_t KsB = QsB + AQ_HALFS * 2;
    const uint32_t VsB = KsB + 2 * AK_HALFS * 2;
    // barriers: kfull[2]=+0,+8  kempty[2]=+16,+24  vfull[2]=+32,+40
    //           vempty[2]=+48,+56  qbar=+64
    const uint32_t barB = smemBase + ATTN_DATA_BYTES;

    const int tile = blockIdx.x;
    const int h    = blockIdx.y;

    int seq_start = 0, q0 = 0;
    {
        int acc = 0, start = 0;
        #pragma unroll
        for (int s = 0; s < 8; s++) {
            int nt = c_seqlen[s] >> 7;
            if (tile >= acc && tile < acc + nt) {
                seq_start = start; q0 = (tile - acc) << 7;
            }
            acc += nt; start += c_seqlen[s];
        }
    }

    const int tid = threadIdx.x, lane = tid & 31, warp = tid >> 5;
    const int lq = lane >> 2, lr = lane & 3;
    const int nkv = (q0 >> 6) + 2;

    const size_t q_row0  = (size_t)(seq_start + q0) * QKV3 + (size_t)h * HD;
    const size_t kv_row0 = (size_t)seq_start * QKV3 + DIM + (size_t)h * HD;

    const int tr = lane & 7, th = (lane >> 3) & 1, tq = lane >> 4;
    const uint32_t aoff = (uint32_t)(((warp * 16 + tr + th * 8) * AQ_STRIDE + tq * 8) * 2);
    const uint32_t koff = (uint32_t)(((tr + th * 8) * AK_STRIDE + tq * 8) * 2);
    const uint32_t voff = (uint32_t)(((lane & 15) * AV_STRIDE + ((lane >> 4) << 3)) * 2);

    if (tid < 8) mbar_init(barB + 8 * tid, 256);
    if (tid == 8) mbar_init(barB + 64, 256);
    __syncthreads();

    // prologue: Q, then K0,V0,K1,V1 (cp arrive = this thread's prior cps done)
    {
        #pragma unroll
        for (int j = 0; j < 8; j++) {
            int i = tid + j * 256;
            int r = i >> 4, g = (i & 15) << 3;
            cp_async16(Qs + r * AQ_STRIDE + g, qkv + q_row0 + (size_t)r * QKV3 + g);
        }
        cp_mbar_arrive(barB + 64);
    }
    #pragma unroll
    for (int t = 0; t < 2; t++) {
        __half* Kd = Ks + t * AK_HALFS;
        __half* Vd = Vs + t * AV_HALFS;
        const __half* kb = qkv + kv_row0 + (size_t)(t * 64) * QKV3;
        #pragma unroll
        for (int j = 0; j < 4; j++) {
            int i = tid + j * 256;
            int r = i >> 4, g = (i & 15) << 3;
            cp_async16(Kd + r * AK_STRIDE + g, kb + (size_t)r * QKV3 + g);
        }
        cp_mbar_arrive(barB + 8 * t);        // kfull[t]
        #pragma unroll
        for (int j = 0; j < 4; j++) {
            int i = tid + j * 256;
            int r = i >> 4, g = (i & 15) << 3;
            cp_async16(Vd + r * AV_STRIDE + g, kb + (size_t)r * QKV3 + DIM + g);
        }
        cp_mbar_arrive(barB + 32 + 8 * t);   // vfull[t]
    }

    float oacc[16][4];
    #pragma unroll
    for (int nf = 0; nf < 16; nf++)
        #pragma unroll
        for (int e = 0; e < 4; e++) oacc[nf][e] = 0.f;
    float m0 = -1e30f, m1 = -1e30f, l0 = 0.f, l1 = 0.f;
    const float scale = 0.08838834764831845f;   // 1/sqrt(128)

    const int qbase_warp = q0 + warp * 16;
    uint32_t pkl[8], pkh[8];   // P(t-1) fp16 packs

    mbar_wait(barB + 64, 0);   // Q ready

    for (int t = 0; t < nkv; t++) {
        const int b = t & 1;
        const int j0 = t << 6;
        const bool valid_t = (j0 <= qbase_warp + 15);
        const bool valid_p = (t >= 1) && (((t - 1) << 6) <= qbase_warp + 15);

        // ---- S(t) = Q K(t)^T ----
        mbar_wait(barB + 8 * b, (uint32_t)((t >> 1) & 1));   // kfull[b]
        float sacc[8][4];
        if (valid_t) {
            const uint32_t KbB = KsB + (uint32_t)(b * AK_HALFS * 2);
            #pragma unroll
            for (int nf = 0; nf < 8; nf++)
                #pragma unroll
                for (int e = 0; e < 4; e++) sacc[nf][e] = 0.f;
            #pragma unroll
            for (int ks = 0; ks < 8; ks++) {
                const uint32_t kOff = (uint32_t)(ks * 32);
                uint32_t af[4];
                ldsm_x4(af, QsB + aoff + kOff);
                #pragma unroll
                for (int nb = 0; nb < 4; nb++) {
                    uint32_t bq[4];
                    ldsm_x4(bq, KbB + koff + (uint32_t)(nb * 16 * AK_STRIDE * 2) + kOff);
                    uint32_t bf0[2] = {bq[0], bq[2]};
                    uint32_t bf1[2] = {bq[1], bq[3]};
                    mma_f16(sacc[2 * nb],     af, bf0);
                    mma_f16(sacc[2 * nb + 1], af, bf1);
                }
            }
        }
        mbar_arrive(barB + 16 + 8 * b);   // kempty[b]

        // ---- PV(t-1): issued before softmax(t); overlaps it on the tensor pipe ----
        if (t >= 1) {
            const int bp = (t - 1) & 1;
            mbar_wait(barB + 32 + 8 * bp, (uint32_t)(((t - 1) >> 1) & 1));  // vfull[bp]
            if (valid_p) {
                const uint32_t VbB = VsB + (uint32_t)(bp * AV_HALFS * 2);
                #pragma unroll
                for (int ks = 0; ks < 4; ks++) {
                    uint32_t af[4] = {pkl[2 * ks], pkh[2 * ks],
                                      pkl[2 * ks + 1], pkh[2 * ks + 1]};
                    const uint32_t rowOff = (uint32_t)(ks * 16 * AV_STRIDE * 2);
                    #pragma unroll
                    for (int q = 0; q < 8; q++) {
                        uint32_t v[4];
                        ldsm_x4_t(v, VbB + voff + rowOff + (uint32_t)(q * 32));
                        uint32_t bf0[2] = {v[0], v[1]};
                        uint32_t bf1[2] = {v[2], v[3]};
                        mma_f16(oacc[2 * q],     af, bf0);
                        mma_f16(oacc[2 * q + 1], af, bf1);
                    }
                }
            }
            mbar_arrive(barB + 48 + 8 * bp);   // vempty[bp]
        }

        // ---- softmax(t) -> P(t); rescale oacc (after PV(t-1) contribution) ----
        if (valid_t) {
            const bool diag = (j0 + 63 > qbase_warp);
            const int qr0 = qbase_warp + lq;
            const int qr1 = qr0 + 8;
            float mx0 = -1e30f, mx1 = -1e30f;
            #pragma unroll
            for (int nf = 0; nf < 8; nf++) {
                #pragma unroll
                for (int e = 0; e < 4; e++) {
                    float s = sacc[nf][e] * scale;
                    if (diag) {
                        int kc = j0 + nf * 8 + lr * 2 + (e & 1);
                        int qr = (e < 2) ? qr0 : qr1;
                        if (kc > qr) s = -1e30f;
                    }
                    sacc[nf][e] = s;
                }
                mx0 = fmaxf(mx0, fmaxf(sacc[nf][0], sacc[nf][1]));
                mx1 = fmaxf(mx1, fmaxf(sacc[nf][2], sacc[nf][3]));
            }
            mx0 = fmaxf(mx0, __shfl_xor_sync(0xffffffffu, mx0, 1));
            mx0 = fmaxf(mx0, __shfl_xor_sync(0xffffffffu, mx0, 2));
            mx1 = fmaxf(mx1, __shfl_xor_sync(0xffffffffu, mx1, 1));
            mx1 = fmaxf(mx1, __shfl_xor_sync(0xffffffffu, mx1, 2));

            float mn0 = fmaxf(m0, mx0), mn1 = fmaxf(m1, mx1);
            float c0 = exp2f((m0 - mn0) * LOG2E), c1 = exp2f((m1 - mn1) * LOG2E);
            float s0 = 0.f, s1 = 0.f;
            #pragma unroll
            for (int nf = 0; nf < 8; nf++) {
                float p0 = exp2f((sacc[nf][0] - mn0) * LOG2E);
                float p1 = exp2f((sacc[nf][1] - mn0) * LOG2E);
                float p2 = exp2f((sacc[nf][2] - mn1) * LOG2E);
                float p3 = exp2f((sacc[nf][3] - mn1) * LOG2E);
                s0 += p0 + p1; s1 += p2 + p3;
                __half2 hl = __floats2half2_rn(p0, p1);
                __half2 hh = __floats2half2_rn(p2, p3);
                pkl[nf] = *reinterpret_cast<uint32_t*>(&hl);
                pkh[nf] = *reinterpret_cast<uint32_t*>(&hh);
            }
            s0 += __shfl_xor_sync(0xffffffffu, s0, 1);
            s0 += __shfl_xor_sync(0xffffffffu, s0, 2);
            s1 += __shfl_xor_sync(0xffffffffu, s1, 1);
            s1 += __shfl_xor_sync(0xffffffffu, s1, 2);
            l0 = l0 * c0 + s0;
            l1 = l1 * c1 + s1;
            m0 = mn0; m1 = mn1;
            #pragma unroll
            for (int nf = 0; nf < 16; nf++) {
                oacc[nf][0] *= c0; oacc[nf][1] *= c0;
                oacc[nf][2] *= c1; oacc[nf][3] *= c1;
            }
        }

        // ---- producers ----
        if (t + 2 < nkv) {   // K(t+2) into buffer b (K(t) consumed)
            mbar_wait(barB + 16 + 8 * b, (uint32_t)((t >> 1) & 1));   // kempty[b]
            __half* Kd = Ks + b * AK_HALFS;
            const __half* kb = qkv + kv_row0 + (size_t)((t + 2) * 64) * QKV3;
            #pragma unroll
            for (int j = 0; j < 4; j++) {
                int i = tid + j * 256;
                int r = i >> 4, g = (i & 15) << 3;
                cp_async16(Kd + r * AK_STRIDE + g, kb + (size_t)r * QKV3 + g);
            }
            cp_mbar_arrive(barB + 8 * b);
        }
        if (t >= 1 && t + 1 < nkv) {   // V(t+1) into buffer (t+1)&1 (V(t-1) consumed)
            const int bn = (t + 1) & 1;
            mbar_wait(barB + 48 + 8 * bn, (uint32_t)(((t - 1) >> 1) & 1));  // vempty[bn]
            __half* Vd = Vs + bn * AV_HALFS;
            const __half* kb = qkv + kv_row0 + (size_t)((t + 1) * 64) * QKV3;
            #pragma unroll
            for (int j = 0; j < 4; j++) {
                int i = tid + j * 256;
                int r = i >> 4, g = (i & 15) << 3;
                cp_async16(Vd + r * AV_STRIDE + g, kb + (size_t)r * QKV3 + DIM + g);
            }
            cp_mbar_arrive(barB + 32 + 8 * bn);
        }
    }

    // ---- drain: PV(nkv-1) ----
    {
        const int tl = nkv - 1;
        const int bp = tl & 1;
        mbar_wait(barB + 32 + 8 * bp, (uint32_t)((tl >> 1) & 1));   // vfull[bp]
        if ((tl << 6) <= qbase_warp + 15) {
            const uint32_t VbB = VsB + (uint32_t)(bp * AV_HALFS * 2);
            #pragma unroll
            for (int ks = 0; ks < 4; ks++) {
                uint32_t af[4] = {pkl[2 * ks], pkh[2 * ks],
                                  pkl[2 * ks + 1], pkh[2 * ks + 1]};
                const uint32_t rowOff = (uint32_t)(ks * 16 * AV_STRIDE * 2);
                #pragma unroll
                for (int q = 0; q < 8; q++) {
                    uint32_t v[4];
                    ldsm_x4_t(v, VbB + voff + rowOff + (uint32_t)(q * 32));
                    uint32_t bf0[2] = {v[0], v[1]};
                    uint32_t bf1[2] = {v[2], v[3]};
                    mma_f16(oacc[2 * q],     af, bf0);
                    mma_f16(oacc[2 * q + 1], af, bf1);
                }
            }
        }
    }

    // epilogue -> fp16 (feeds out_proj fp16 GEMM)
    float inv0 = 1.f / l0, inv1 = 1.f / l1;
    int t0 = seq_start + q0 + warp * 16 + lq;
    __half* ob = out + (size_t)t0 * DIM + (size_t)h * HD;
    #pragma unroll
    for (int nf = 0; nf < 16; nf++) {
        int c = nf * 8 + lr * 2;
        *reinterpret_cast<__half2*>(ob + c) =
            __floats2half2_rn(oacc[nf][0] * inv0, oacc[nf][1] * inv0);
        *reinterpret_cast<__half2*>(ob + (size_t)8 * DIM + c) =
            __floats2half2_rn(oacc[nf][2] * inv1, oacc[nf][3] * inv1);
    }
}

// ---------------- launch ----------------
extern "C" void kernel_launch(void* const* d_in, const int* in_sizes, int n_in,
                              void* d_out, int out_size)
{
    const float* hidden     = (const float*)d_in[0];
    const float* ln1_w      = (const float*)d_in[1];
    const float* ln2_w      = (const float*)d_in[2];
    const float* in_proj_w  = (const float*)d_in[3];
    const float* in_proj_b  = (const float*)d_in[4];
    const float* out_proj_w = (const float*)d_in[5];
    const float* out_proj_b = (const float*)d_in[6];
    const float* gate_w     = (const float*)d_in[7];
    const float* up_w       = (const float*)d_in[8];
    const float* down_w     = (const float*)d_in[9];
    float* out = (float*)d_out;

    __half *p_ln, *p_qkv, *p_attn, *p_gu;
    float  *p_h2;
    __half *p_wqkv, *p_wout, *p_wgu, *p_wdown;
    cudaGetSymbolAddress((void**)&p_ln,    g_ln);
    cudaGetSymbolAddress((void**)&p_qkv,   g_qkv);
    cudaGetSymbolAddress((void**)&p_attn,  g_attn);
    cudaGetSymbolAddress((void**)&p_h2,    g_h2);
    cudaGetSymbolAddress((void**)&p_gu,    g_gu);
    cudaGetSymbolAddress((void**)&p_wqkv,  g_wqkv);
    cudaGetSymbolAddress((void**)&p_wout,  g_wout);
    cudaGetSymbolAddress((void**)&p_wgu,   g_wgu);
    cudaGetSymbolAddress((void**)&p_wdown, g_wdown);

    cudaFuncSetAttribute((const void*)gemm_f16_kernel,
                         cudaFuncAttributeMaxDynamicSharedMemorySize, GEMM_SMEM_BYTES);
    cudaFuncSetAttribute((const void*)attn_kernel,
                         cudaFuncAttributeMaxDynamicSharedMemorySize, ATTN_SMEM_BYTES);

    int n4;
    // launch 0: qkv weight conversion
    n4 = (QKV3 * DIM) / 4;
    cvtw_kernel<<<(n4 + 255) / 256, 256>>>((const float4*)in_proj_w, (__half2*)p_wqkv, n4);
    // launch 1: rmsnorm1 (fp16 out)
    rmsnorm_kernel<<<TOTAL, 256>>>(hidden, ln1_w, p_ln);
    // launch 2: qkv projection (fp16 out)
    gemm_f16_kernel<<<dim3(QKV3 / 128, TOTAL / 128), 256, GEMM_SMEM_BYTES>>>(
        p_ln, p_wqkv, in_proj_b, nullptr, nullptr, p_qkv, nullptr, TOTAL, QKV3, DIM);
    // launch 3: attention (ncu capture slot)
    attn_kernel<<<dim3(TOTAL / 128, HEADS), 256, ATTN_SMEM_BYTES>>>(p_qkv, p_attn);
    // launch 4: out-proj weight conversion
    n4 = (DIM * DIM) / 4;
    cvtw_kernel<<<(n4 + 255) / 256, 256>>>((const float4*)out_proj_w, (__half2*)p_wout, n4);
    // launch 5: out projection + residual (fp32 out)
    gemm_f16_kernel<<<dim3(DIM / 128, TOTAL / 128), 256, GEMM_SMEM_BYTES>>>(
        p_attn, p_wout, out_proj_b, hidden, p_h2, nullptr, nullptr, TOTAL, DIM, DIM);
    // launch 6: rmsnorm2 (fp16 out)
    rmsnorm_kernel<<<TOTAL, 256>>>(p_h2, ln2_w, p_ln);
    // launch 7: gate+up interleaved weight conversion
    n4 = (FDIM * DIM) / 4;
    cvtw2_kernel<<<(n4 + 255) / 256, 256>>>((const float4*)gate_w, (const float4*)up_w,
                                            (__half2*)p_wgu, n4);
    // launch 8: fused gate/up projection + sigmoid-gate epilogue (fp16 out)
    gemm_f16_kernel<<<dim3((2 * FDIM) / 128, TOTAL / 128), 256, GEMM_SMEM_BYTES>>>(
        p_ln, p_wgu, nullptr, nullptr, nullptr, nullptr, p_gu, TOTAL, 2 * FDIM, DIM);
    // launch 9: down weight conversion
    cvtw_kernel<<<(n4 + 255) / 256, 256>>>((const float4*)down_w, (__half2*)p_wdown, n4);
    // launch 10: down projection + residual -> output (fp32)
    gemm_f16_kernel<<<dim3(DIM / 128, TOTAL / 128), 256, GEMM_SMEM_BYTES>>>(
        p_gu, p_wdown, nullptr, p_h2, out, nullptr, nullptr, TOTAL, DIM, FDIM);
}